// round 17
// baseline (speedup 1.0000x reference)
#include <cuda_runtime.h>

#define B_  16
#define C_  64
#define H_  224
#define W_  224
#define O_  128
#define PH_ 16
#define OH_ 222
#define OW_ 222
#define HW56 (H_ * 56)

__device__ float g_s[(size_t)B_ * H_ * W_];

__device__ __forceinline__ float4 ldcs4(const float4* p) {
    float4 v;
    asm volatile("ld.global.cs.v4.f32 {%0,%1,%2,%3}, [%4];"
                 : "=f"(v.x), "=f"(v.y), "=f"(v.z), "=f"(v.w) : "l"(p));
    return v;
}
__device__ __forceinline__ void stcs2(float* p, float a, float b) {
    asm volatile("st.global.cs.v2.f32 [%0], {%1,%2};" :: "l"(p), "f"(a), "f"(b));
}

// ---------- k1: channel reduction (R15/R16 winner, verbatim) ----------
__global__ __launch_bounds__(128, 6) void k1_reduce(
    const float* __restrict__ x,
    const float* __restrict__ pw,
    const float* __restrict__ pb)
{
    __shared__ float4 bs[64];

    const int t = threadIdx.x;
    if (t < 64) {
        const float4* pb4 = (const float4*)pb;
        float4 a = make_float4(0.f, 0.f, 0.f, 0.f);
        #pragma unroll 16
        for (int c = 0; c < C_; c++) {
            float4 v = __ldg(pb4 + c * 64 + t);
            a.x += v.x; a.y += v.y; a.z += v.z; a.w += v.w;
        }
        bs[t] = a;
    }

    const int p   = blockIdx.x * 128 + t;
    const int col = p % 56;
    const int bh  = p / 56;
    const int h   = bh % H_;
    const int hh  = h & (PH_ - 1);
    const int w4  = col & 3;

    const float4* xp = (const float4*)x + (size_t)(bh / H_) * C_ * HW56
                                        + (size_t)h * 56 + col;
    const float4* wp = (const float4*)pw + hh * 4 + w4;

    __syncthreads();
    float4 acc = bs[hh * 4 + w4];

    #pragma unroll 2
    for (int c0 = 0; c0 < C_; c0 += 8) {
        float4 xv[8];
        #pragma unroll
        for (int j = 0; j < 8; j++)
            xv[j] = ldcs4(xp + (size_t)(c0 + j) * HW56);
        #pragma unroll
        for (int j = 0; j < 8; j++) {
            float4 wv = __ldg(wp + (c0 + j) * 64);
            acc.x = fmaf(xv[j].x, wv.x, acc.x);
            acc.y = fmaf(xv[j].y, wv.y, acc.y);
            acc.z = fmaf(xv[j].z, wv.z, acc.z);
            acc.w = fmaf(xv[j].w, wv.w, acc.w);
        }
    }
    ((float4*)g_s)[p] = acc;
}

// ---------- k2: 3x3 conv, 4 rows x 4 cols per thread ----------
// block = 224 threads = 4 output rows x 56 col-quads; OCG=32 channels.
// grid = (B * 56, 4)
#define OCG 32
__global__ __launch_bounds__(224) void k2_conv3x3(
    const float* __restrict__ comp,
    float* __restrict__ out)
{
    const int gx = blockIdx.x;
    const int b  = gx / 56;
    const int i0 = (gx % 56) * 4;            // 0,4,...,220
    const int o0 = blockIdx.y * OCG;

    __shared__ float srow[6][232];           // 6 s-rows, padded width
    __shared__ float csh[OCG * 12];

    const int t = threadIdx.x;

    // stage up to 6 s-rows (clamp at H, zero-pad cols 224..231)
    const float* sp = g_s + ((size_t)b * H_ + i0) * W_;
    #pragma unroll
    for (int rr = 0; rr < 6; rr++) {
        float v = 0.f;
        if (i0 + rr < H_) v = __ldg(sp + rr * W_ + t);
        srow[rr][t] = v;
        if (t < 8) srow[rr][224 + t] = 0.f;
    }
    for (int idx = t; idx < OCG * 9; idx += 224) {
        int k = idx / 9, m = idx % 9;
        csh[k * 12 + m] = comp[(o0 + k) * 9 + m];
    }
    __syncthreads();

    const int r  = t / 56;                   // output row in block (0..3)
    const int q  = t % 56;
    const int j0 = q * 4;                    // 0,4,...,220
    const int i  = i0 + r;
    if (i >= OH_) return;
    const bool full = (j0 + 4 <= OW_);       // q==55 -> only 2 cols valid

    // 3 rows x 6 cols window (16B-aligned row starts: 232*4 and j0*4 both %16==0)
    float sv[3][6];
    #pragma unroll
    for (int d = 0; d < 3; d++) {
        float4 a  = *(const float4*)&srow[r + d][j0];
        float2 bb = *(const float2*)&srow[r + d][j0 + 4];
        sv[d][0] = a.x; sv[d][1] = a.y; sv[d][2] = a.z; sv[d][3] = a.w;
        sv[d][4] = bb.x; sv[d][5] = bb.y;
    }

    const float4* csh4 = (const float4*)csh;
    size_t base = (((size_t)b * O_ + o0) * OH_ + i) * OW_ + j0;

    #pragma unroll 4
    for (int k = 0; k < OCG; k++) {
        float4 w0 = csh4[k * 3 + 0];
        float4 w1 = csh4[k * 3 + 1];
        float4 w2 = csh4[k * 3 + 2];
        const float wk[9] = {w0.x, w0.y, w0.z, w0.w, w1.x, w1.y, w1.z, w1.w, w2.x};

        float acc[4];
        #pragma unroll
        for (int c = 0; c < 4; c++) {
            float a = wk[0] * sv[0][c];
            #pragma unroll
            for (int d = 0; d < 3; d++)
                #pragma unroll
                for (int e = 0; e < 3; e++)
                    if (d + e > 0) a = fmaf(wk[d * 3 + e], sv[d][c + e], a);
            acc[c] = a;
        }

        float* op = out + base + (size_t)k * (OH_ * OW_);
        stcs2(op, acc[0], acc[1]);
        if (full) stcs2(op + 2, acc[2], acc[3]);
    }
}

extern "C" void kernel_launch(void* const* d_in, const int* in_sizes, int n_in,
                              void* d_out, int out_size)
{
    const float* x    = (const float*)d_in[0];
    const float* pw   = (const float*)d_in[1];
    const float* pb   = (const float*)d_in[2];
    const float* comp = (const float*)d_in[3];
    float* out = (float*)d_out;

    k1_reduce<<<(B_ * H_ * 56) / 128, 128>>>(x, pw, pb);
    dim3 g2(B_ * 56, O_ / OCG);
    k2_conv3x3<<<g2, 224>>>(comp, out);
}